// round 15
// baseline (speedup 1.0000x reference)
#include <cuda_runtime.h>
#include <cuda_fp16.h>
#include <cstdint>

#define BATCH 16
#define DIM   256
#define NSEQ  8192
#define HEADS 4
#define DHEAD 32
#define HID   128

// Scratch (device globals — no runtime allocation allowed)
__device__ float g_C[BATCH * HEADS * DHEAD * DHEAD];
__device__ float g_S[BATCH * HEADS * DHEAD];
__device__ uint16_t g_Wh[384 * DIM];                        // W fp16 hi plane
__device__ uint16_t g_Wm[384 * DIM];                        // W fp16 mid plane
__device__ uint16_t g_Gh[BATCH * DIM * HID];                // G fp16 (hi only)
__device__ uint16_t g_qh[(size_t)BATCH * 128 * NSEQ];       // q fp16 (hi only)
__device__ uint16_t g_ekh[(size_t)BATCH * 128 * NSEQ];      // exp(k) fp16 planes
__device__ uint16_t g_ekm[(size_t)BATCH * 128 * NSEQ];
__device__ uint16_t g_vh[(size_t)BATCH * 128 * NSEQ];       // v fp16 planes
__device__ uint16_t g_vm[(size_t)BATCH * 128 * NSEQ];

// ===================== mma.sync f16 m16n8k16 + ldmatrix + cp.async ==================
#define MMA_F16(d, a0, a1, a2, a3, b0, b1) \
    asm volatile("mma.sync.aligned.m16n8k16.row.col.f32.f16.f16.f32 " \
        "{%0,%1,%2,%3}, {%4,%5,%6,%7}, {%8,%9}, {%0,%1,%2,%3};" \
        : "+f"((d)[0]), "+f"((d)[1]), "+f"((d)[2]), "+f"((d)[3]) \
        : "r"(a0), "r"(a1), "r"(a2), "r"(a3), "r"(b0), "r"(b1))

#define LDSM_X4(r0, r1, r2, r3, addr) \
    asm volatile("ldmatrix.sync.aligned.m8n8.x4.shared.b16 {%0,%1,%2,%3}, [%4];" \
        : "=r"(r0), "=r"(r1), "=r"(r2), "=r"(r3) : "r"(addr))

#define LDSM_X4_T(r0, r1, r2, r3, addr) \
    asm volatile("ldmatrix.sync.aligned.m8n8.x4.trans.shared.b16 {%0,%1,%2,%3}, [%4];" \
        : "=r"(r0), "=r"(r1), "=r"(r2), "=r"(r3) : "r"(addr))

#define CP16(dst, src) \
    asm volatile("cp.async.cg.shared.global [%0], [%1], 16;" :: "r"(dst), "l"(src) : "memory")
#define CP_COMMIT() asm volatile("cp.async.commit_group;" ::: "memory")
#define CP_WAIT0()  asm volatile("cp.async.wait_group 0;" ::: "memory")

__device__ __forceinline__ uint32_t smem_u32(const void* p) {
    uint32_t a;
    asm("{ .reg .u64 t; cvta.to.shared.u64 t, %1; cvt.u32.u64 %0, t; }" : "=r"(a) : "l"(p));
    return a;
}
__device__ __forceinline__ uint32_t pack_f16(float lo, float hi) {
    uint32_t r;
    asm("cvt.rn.f16x2.f32 %0, %1, %2;" : "=r"(r) : "f"(hi), "f"(lo));
    return r;
}
__device__ __forceinline__ void f16_split2(float x, float y, uint32_t& hp, uint32_t& mp) {
    hp = pack_f16(x, y);
    __half2 h = *reinterpret_cast<__half2*>(&hp);
    float fx = __low2float(h);
    float fy = __high2float(h);
    mp = pack_f16(x - fx, y - fy);
}

#define AKP 40
#define BNP 136

struct PipeSmem {
    uint16_t Ah[2][128 * AKP];
    uint16_t Am[2][128 * AKP];
    uint16_t Bh[2][32 * BNP];
    uint16_t Bm[2][32 * BNP];
};
#define PIPE_SMEM ((int)sizeof(PipeSmem))

// ---------- K0: zero accumulators + split W into fp16 planes (fused) ----------
__global__ void k_init(const float* __restrict__ w) {
    int i = blockIdx.x * 256 + threadIdx.x;
    if (i < BATCH * HEADS * DHEAD * DHEAD) g_C[i] = 0.0f;
    if (i < BATCH * HEADS * DHEAD)         g_S[i] = 0.0f;
    if (i < 384 * DIM / 2) {
        float2 t = ((const float2*)w)[i];
        uint32_t h, m;
        f16_split2(t.x, t.y, h, m);
        ((uint32_t*)g_Wh)[i] = h;
        ((uint32_t*)g_Wm)[i] = m;
    }
}

// ================= mma core (128x128 tile, 8 warps 2m x 4n); MID = include cross terms ======
template <bool MID>
__device__ __forceinline__ void mma_chunk_t(uint32_t aBaseH, uint32_t aBaseM,
                                            uint32_t bBaseH, uint32_t bBaseM,
                                            float acc[4][4][4],
                                            int warp_m, int warp_n, int lane) {
    const int lr8 = lane & 15;
    const int lh  = lane >> 4;
#pragma unroll
    for (int ks = 0; ks < 2; ks++) {
        uint32_t bh[4][2], bm[4][2];
#pragma unroll
        for (int np = 0; np < 2; np++) {
            const int n0 = warp_n * 32 + np * 16;
            const uint32_t baddr = (uint32_t)((ks * 16 + lr8) * (BNP * 2) + n0 * 2 + lh * 16);
            LDSM_X4_T(bh[np * 2][0], bh[np * 2][1], bh[np * 2 + 1][0], bh[np * 2 + 1][1],
                      bBaseH + baddr);
            if (MID)
                LDSM_X4_T(bm[np * 2][0], bm[np * 2][1], bm[np * 2 + 1][0], bm[np * 2 + 1][1],
                          bBaseM + baddr);
        }
#pragma unroll
        for (int mt = 0; mt < 4; mt++) {
            const int m0 = warp_m * 64 + mt * 16;
            const uint32_t aaddr = (uint32_t)((m0 + lr8) * (AKP * 2) + ks * 32 + lh * 16);
            uint32_t ah0, ah1, ah2, ah3;
            LDSM_X4(ah0, ah1, ah2, ah3, aBaseH + aaddr);
            uint32_t am0, am1, am2, am3;
            if (MID) LDSM_X4(am0, am1, am2, am3, aBaseM + aaddr);
#pragma unroll
            for (int nt = 0; nt < 4; nt++) {
                MMA_F16(acc[mt][nt], ah0, ah1, ah2, ah3, bh[nt][0], bh[nt][1]);
                if (MID) {
                    MMA_F16(acc[mt][nt], ah0, ah1, ah2, ah3, bm[nt][0], bm[nt][1]);
                    MMA_F16(acc[mt][nt], am0, am1, am2, am3, bh[nt][0], bh[nt][1]);
                }
            }
        }
    }
}

// ---------- K1: qkv = w_qkv @ x  (q/v: 1-pass fp16, k: 3-pass fp16) ----------
__global__ __launch_bounds__(256, 2) void k_qkv_mma(const float* __restrict__ x) {
    extern __shared__ char dsm[];
    PipeSmem* s = (PipeSmem*)dsm;
    const int b       = blockIdx.z;
    const int grp     = blockIdx.y;            // 0=q, 1=k, 2=v
    const int nBase   = blockIdx.x * 128;
    const int tid     = threadIdx.x;
    const int lane    = tid & 31;
    const int wid     = tid >> 5;
    const int warp_m  = wid & 1;
    const int warp_n  = wid >> 1;

    const float* xb = x + (size_t)b * DIM * NSEQ + nBase;
    const uint16_t* WhA = g_Wh + (size_t)(grp * 128) * DIM;
    const uint16_t* WmA = g_Wm + (size_t)(grp * 128) * DIM;

    float acc[4][4][4];
#pragma unroll
    for (int i = 0; i < 4; i++)
#pragma unroll
        for (int j = 0; j < 4; j++)
#pragma unroll
            for (int c = 0; c < 4; c++) acc[i][j][c] = 0.0f;

    const int kb = tid >> 5;
    const int n4 = (tid & 31) << 2;
    const int ar = tid >> 2, asg = tid & 3;

    auto issueA = [&](int st, int k0) {
#pragma unroll
        for (int half = 0; half < 2; half++) {
            const int r = ar + half * 64;
            CP16(smem_u32(&s->Ah[st][r * AKP + asg * 8]), WhA + (size_t)r * DIM + k0 + asg * 8);
            if (grp == 1)
                CP16(smem_u32(&s->Am[st][r * AKP + asg * 8]), WmA + (size_t)r * DIM + k0 + asg * 8);
        }
        CP_COMMIT();
    };
    auto ldgB = [&](float4 pb[4], int k0) {
#pragma unroll
        for (int it = 0; it < 4; it++)
            pb[it] = *(const float4*)(xb + (size_t)(k0 + kb + it * 8) * NSEQ + n4);
    };
    auto cvtB = [&](int st, const float4 pb[4]) {
#pragma unroll
        for (int it = 0; it < 4; it++) {
            const int k = kb + it * 8;
            if (grp == 1) {
                uint32_t h01, m01, h23, m23;
                f16_split2(pb[it].x, pb[it].y, h01, m01);
                f16_split2(pb[it].z, pb[it].w, h23, m23);
                *(uint2*)&s->Bh[st][k * BNP + n4] = make_uint2(h01, h23);
                *(uint2*)&s->Bm[st][k * BNP + n4] = make_uint2(m01, m23);
            } else {
                *(uint2*)&s->Bh[st][k * BNP + n4] =
                    make_uint2(pack_f16(pb[it].x, pb[it].y), pack_f16(pb[it].z, pb[it].w));
            }
        }
    };

    float4 pb[4];
    ldgB(pb, 0);
    issueA(0, 0);

    for (int chunk = 0; chunk < 8; chunk++) {
        const int cur = chunk & 1;
        CP_WAIT0();
        cvtB(cur, pb);
        __syncthreads();
        if (chunk < 7) {
            ldgB(pb, (chunk + 1) * 32);
            issueA(cur ^ 1, (chunk + 1) * 32);
        }
        if (grp == 1)
            mma_chunk_t<true>(smem_u32(s->Ah[cur]), smem_u32(s->Am[cur]),
                              smem_u32(s->Bh[cur]), smem_u32(s->Bm[cur]),
                              acc, warp_m, warp_n, lane);
        else
            mma_chunk_t<false>(smem_u32(s->Ah[cur]), smem_u32(s->Am[cur]),
                               smem_u32(s->Bh[cur]), smem_u32(s->Bm[cur]),
                               acc, warp_m, warp_n, lane);
    }

    const int lg = lane >> 2, lc = lane & 3;
    float sr0[4] = {0.f, 0.f, 0.f, 0.f};
    float sr8[4] = {0.f, 0.f, 0.f, 0.f};
#pragma unroll
    for (int mt = 0; mt < 4; mt++) {
        const int row0 = warp_m * 64 + mt * 16 + lg;
#pragma unroll
        for (int nt = 0; nt < 4; nt++) {
            const int cn = nBase + warp_n * 32 + nt * 8 + (lc << 1);
            float v0 = acc[mt][nt][0], v1 = acc[mt][nt][1];
            float v2 = acc[mt][nt][2], v3 = acc[mt][nt][3];
            const size_t wi0 = (((size_t)b * 128 + row0) * NSEQ + cn) >> 1;
            const size_t wi1 = (((size_t)b * 128 + row0 + 8) * NSEQ + cn) >> 1;
            if (grp == 0) {
                ((uint32_t*)g_qh)[wi0] = pack_f16(v0, v1);
                ((uint32_t*)g_qh)[wi1] = pack_f16(v2, v3);
            } else if (grp == 1) {
                v0 = __expf(v0); v1 = __expf(v1); v2 = __expf(v2); v3 = __expf(v3);
                sr0[mt] += v0 + v1;
                sr8[mt] += v2 + v3;
                uint32_t h01, m01, h23, m23;
                f16_split2(v0, v1, h01, m01);
                f16_split2(v2, v3, h23, m23);
                ((uint32_t*)g_ekh)[wi0] = h01; ((uint32_t*)g_ekm)[wi0] = m01;
                ((uint32_t*)g_ekh)[wi1] = h23; ((uint32_t*)g_ekm)[wi1] = m23;
            } else {
                uint32_t h01, m01, h23, m23;
                f16_split2(v0, v1, h01, m01);
                f16_split2(v2, v3, h23, m23);
                ((uint32_t*)g_vh)[wi0] = h01; ((uint32_t*)g_vm)[wi0] = m01;
                ((uint32_t*)g_vh)[wi1] = h23; ((uint32_t*)g_vm)[wi1] = m23;
            }
        }
    }
    if (grp == 1) {
#pragma unroll
        for (int mt = 0; mt < 4; mt++) {
            float s0 = sr0[mt], s8 = sr8[mt];
            s0 += __shfl_xor_sync(0xFFFFFFFFu, s0, 1);
            s0 += __shfl_xor_sync(0xFFFFFFFFu, s0, 2);
            s8 += __shfl_xor_sync(0xFFFFFFFFu, s8, 1);
            s8 += __shfl_xor_sync(0xFFFFFFFFu, s8, 2);
            if (lc == 0) {
                const int row0 = warp_m * 64 + mt * 16 + lg;
                atomicAdd(&g_S[b * 128 + row0], s0);
                atomicAdd(&g_S[b * 128 + row0 + 8], s8);
            }
        }
    }
}

// ---------- K2: C[b,h] += ek-slab @ v-slab^T (3-pass fp16, cp.async pipelined, occ 3) ----------
struct CtxSmem {
    uint16_t Ekh[2][32 * BNP];
    uint16_t Ekm[2][32 * BNP];
    uint16_t Vh[2][32 * BNP];
    uint16_t Vm[2][32 * BNP];
};
#define CTX_SMEM ((int)sizeof(CtxSmem))

__global__ __launch_bounds__(256, 3) void k_ctx_mma() {
    extern __shared__ char dsm[];
    CtxSmem* s = (CtxSmem*)dsm;
    __shared__ float Cred[32 * 32];

    const int slab = blockIdx.x, h = blockIdx.y, b = blockIdx.z;
    const int tid  = threadIdx.x;
    const int lane = tid & 31;
    const int wid  = tid >> 5;
    const int lg = lane >> 2, lc = lane & 3;
    const int lr8 = lane & 15, lh = lane >> 4;

    for (int i = tid; i < 1024; i += 256) Cred[i] = 0.0f;

    const size_t rowb = (size_t)b * 128 + h * 32;
    const size_t noff = (size_t)slab * 512;
    const uint16_t* ekh = g_ekh + rowb * NSEQ + noff;
    const uint16_t* ekm = g_ekm + rowb * NSEQ + noff;
    const uint16_t* vh  = g_vh  + rowb * NSEQ + noff;
    const uint16_t* vm  = g_vm  + rowb * NSEQ + noff;

    float acc[2][4][4];
#pragma unroll
    for (int i = 0; i < 2; i++)
#pragma unroll
        for (int j = 0; j < 4; j++)
#pragma unroll
            for (int c = 0; c < 4; c++) acc[i][j][c] = 0.0f;

    const int cr = tid >> 4, csg = tid & 15;

    auto issue = [&](int st, int chunk) {
        const int cn = chunk * 128;
#pragma unroll
        for (int it = 0; it < 2; it++) {
            const int r = cr + it * 16;
            const size_t so = (size_t)r * NSEQ + cn + csg * 8;
            const uint32_t doff = (uint32_t)(r * BNP + csg * 8) * 2;
            CP16(smem_u32(s->Ekh[st]) + doff, ekh + so);
            CP16(smem_u32(s->Ekm[st]) + doff, ekm + so);
            CP16(smem_u32(s->Vh[st]) + doff,  vh + so);
            CP16(smem_u32(s->Vm[st]) + doff,  vm + so);
        }
        CP_COMMIT();
    };

    issue(0, 0);

    for (int chunk = 0; chunk < 4; chunk++) {
        const int cur = chunk & 1;
        CP_WAIT0();
        __syncthreads();
        if (chunk < 3) issue(cur ^ 1, chunk + 1);

        uint32_t bh[4][2], bm[4][2];
        {
            const int e    = (lane & 7) + ((lane >> 4) << 3);
            const int koff = ((lane >> 3) & 1) << 3;
#pragma unroll
            for (int np = 0; np < 2; np++) {
                const uint32_t baddr =
                    (uint32_t)((np * 16 + e) * (BNP * 2) + (wid * 16 + koff) * 2);
                LDSM_X4(bh[np * 2][0], bh[np * 2][1], bh[np * 2 + 1][0], bh[np * 2 + 1][1],
                        smem_u32(s->Vh[cur]) + baddr);
                LDSM_X4(bm[np * 2][0], bm[np * 2][1], bm[np * 2 + 1][0], bm[np * 2 + 1][1],
                        smem_u32(s->Vm[cur]) + baddr);
            }
        }
#pragma unroll
        for (int mt = 0; mt < 2; mt++) {
            const uint32_t aaddr = (uint32_t)((mt * 16 + lr8) * (BNP * 2) + wid * 32 + lh * 16);
            uint32_t ah0, ah1, ah2, ah3, am0, am1, am2, am3;
            LDSM_X4(ah0, ah1, ah2, ah3, smem_u32(s->Ekh[cur]) + aaddr);
            LDSM_X4(am0, am1, am2, am3, smem_u32(s->Ekm[cur]) + aaddr);
#pragma unroll
            for (int nt = 0; nt < 4; nt++) {
                MMA_F16(acc[mt][nt], ah0, ah1, ah2, ah3, bh[nt][0], bh[nt][1]);
                MMA_F16(acc[mt][nt], ah0, ah1, ah2, ah3, bm[nt][0], bm[nt][1]);
                MMA_F16(acc[mt][nt], am0, am1, am2, am3, bh[nt][0], bh[nt][1]);
            }
        }
    }

    __syncthreads();
#pragma unroll
    for (int mt = 0; mt < 2; mt++) {
        const int d = mt * 16 + lg;
#pragma unroll
        for (int nt = 0; nt < 4; nt++) {
            const int e = nt * 8 + (lc << 1);
            atomicAdd(&Cred[d * 32 + e],           acc[mt][nt][0]);
            atomicAdd(&Cred[d * 32 + e + 1],       acc[mt][nt][1]);
            atomicAdd(&Cred[(d + 8) * 32 + e],     acc[mt][nt][2]);
            atomicAdd(&Cred[(d + 8) * 32 + e + 1], acc[mt][nt][3]);
        }
    }
    __syncthreads();
    float* Cg = g_C + (size_t)(b * HEADS + h) * 1024;
    for (int i = tid; i < 1024; i += 256) atomicAdd(&Cg[i], Cred[i]);
}

// ---------- K3: G = (w_out-slice @ C)/S -> fp16; thread = (o, 8-d group) ----------
__global__ __launch_bounds__(256) void k_G(const float* __restrict__ w_out) {
    const int h = blockIdx.x, b = blockIdx.y;
    const int o  = blockIdx.z * 64 + (threadIdx.x >> 2);
    const int d0 = (threadIdx.x & 3) * 8;

    __shared__ float Cs[DHEAD * DHEAD];
    __shared__ float Si[DHEAD];

    for (int i = threadIdx.x; i < DHEAD * DHEAD; i += 256)
        Cs[i] = g_C[(size_t)(b * HEADS + h) * DHEAD * DHEAD + i];
    if (threadIdx.x < DHEAD)
        Si[threadIdx.x] = __frcp_rn(g_S[b * 128 + h * DHEAD + threadIdx.x]);
    __syncthreads();

    float wr[DHEAD];
#pragma unroll
    for (int e4 = 0; e4 < DHEAD; e4 += 4) {
        float4 t = *(const float4*)(w_out + (size_t)o * HID + h * DHEAD + e4);
        wr[e4] = t.x; wr[e4 + 1] = t.y; wr[e4 + 2] = t.z; wr[e4 + 3] = t.w;
    }
    const size_t gbase = (size_t)(b * DIM + o) * HID + h * DHEAD;
#pragma unroll
    for (int dd = 0; dd < 8; dd += 2) {
        const int d = d0 + dd;
        float a0 = 0.f, a1 = 0.f;
#pragma unroll
        for (int e = 0; e < DHEAD; e++) {
            a0 += wr[e] * Cs[d * DHEAD + e];
            a1 += wr[e] * Cs[(d + 1) * DHEAD + e];
        }
        a0 *= Si[d]; a1 *= Si[d + 1];
        ((uint32_t*)g_Gh)[(gbase + d) >> 1] = pack_f16(a0, a1);
    }
}

// ---------- K4: out = G_b @ q_b + b_out (1-pass fp16, hi planes only) ----------
struct K4Smem {
    uint16_t Ah[2][128 * AKP];
    uint16_t Bh[2][32 * BNP];
};
#define K4_SMEM ((int)sizeof(K4Smem))

__global__ __launch_bounds__(256, 2) void k_out_mma(const float* __restrict__ bias,
                                                    float* __restrict__ out) {
    extern __shared__ char dsm[];
    K4Smem* s = (K4Smem*)dsm;
    const int b       = blockIdx.z;
    const int rowBase = blockIdx.y * 128;
    const int nBase   = blockIdx.x * 128;
    const int tid     = threadIdx.x;
    const int lane    = tid & 31;
    const int wid     = tid >> 5;
    const int warp_m  = wid & 1;
    const int warp_n  = wid >> 1;

    const uint16_t* GhA = g_Gh + (size_t)(b * DIM + rowBase) * HID;
    const uint16_t* qhB = g_qh + (size_t)b * 128 * NSEQ + nBase;

    float acc[4][4][4];
#pragma unroll
    for (int i = 0; i < 4; i++)
#pragma unroll
        for (int j = 0; j < 4; j++)
#pragma unroll
            for (int c = 0; c < 4; c++) acc[i][j][c] = 0.0f;

    const int ar = tid >> 2, asg = tid & 3;
    const int bk = tid >> 4, bsg = tid & 15;

    auto issue = [&](int st, int k0) {
#pragma unroll
        for (int half = 0; half < 2; half++) {
            const int r = ar + half * 64;
            CP16(smem_u32(&s->Ah[st][r * AKP + asg * 8]), GhA + (size_t)r * HID + k0 + asg * 8);
        }
#pragma unroll
        for (int half = 0; half < 2; half++) {
            const int k = bk + half * 16;
            CP16(smem_u32(&s->Bh[st][k * BNP + bsg * 8]), qhB + (size_t)(k0 + k) * NSEQ + bsg * 8);
        }
        CP_COMMIT();
    };

    issue(0, 0);

    for (int chunk = 0; chunk < 4; chunk++) {
        const int cur = chunk & 1;
        CP_WAIT0();
        __syncthreads();
        if (chunk < 3) issue(cur ^ 1, (chunk + 1) * 32);
        mma_chunk_t<false>(smem_u32(s->Ah[cur]), 0u,
                           smem_u32(s->Bh[cur]), 0u,
                           acc, warp_m, warp_n, lane);
    }

    const int lg = lane >> 2, lc = lane & 3;
    float* outb = out + (size_t)b * DIM * NSEQ;
#pragma unroll
    for (int mt = 0; mt < 4; mt++) {
        const int row0 = rowBase + warp_m * 64 + mt * 16 + lg;
        const float bi0 = bias[row0], bi1 = bias[row0 + 8];
#pragma unroll
        for (int nt = 0; nt < 4; nt++) {
            const int cn = nBase + warp_n * 32 + nt * 8 + (lc << 1);
            *(float2*)(outb + (size_t)row0 * NSEQ + cn) =
                make_float2(acc[mt][nt][0] + bi0, acc[mt][nt][1] + bi0);
            *(float2*)(outb + (size_t)(row0 + 8) * NSEQ + cn) =
                make_float2(acc[mt][nt][2] + bi1, acc[mt][nt][3] + bi1);
        }
    }
}

extern "C" void kernel_launch(void* const* d_in, const int* in_sizes, int n_in,
                              void* d_out, int out_size) {
    const float* x     = (const float*)d_in[0];
    const float* w_qkv = (const float*)d_in[1];
    const float* w_out = (const float*)d_in[2];
    const float* b_out = (const float*)d_in[3];
    float* out = (float*)d_out;

    cudaFuncSetAttribute(k_qkv_mma, cudaFuncAttributeMaxDynamicSharedMemorySize, PIPE_SMEM);
    cudaFuncSetAttribute(k_ctx_mma, cudaFuncAttributeMaxDynamicSharedMemorySize, CTX_SMEM);
    cudaFuncSetAttribute(k_out_mma, cudaFuncAttributeMaxDynamicSharedMemorySize, K4_SMEM);

    k_init<<<257, 256>>>(w_qkv);                 // zeros all g_C/g_S + W planes, every replay
    k_qkv_mma<<<dim3(NSEQ / 128, 3, BATCH), 256, PIPE_SMEM>>>(x);
    k_ctx_mma<<<dim3(16, HEADS, BATCH), 256, CTX_SMEM>>>();
    k_G<<<dim3(HEADS, BATCH, 4), 256>>>(w_out);
    k_out_mma<<<dim3(NSEQ / 128, 2, BATCH), 256, K4_SMEM>>>(b_out, out);
}

// round 16
// speedup vs baseline: 1.1142x; 1.1142x over previous
#include <cuda_runtime.h>
#include <cuda_fp16.h>
#include <cstdint>

#define BATCH 16
#define DIM   256
#define NSEQ  8192
#define HEADS 4
#define DHEAD 32
#define HID   128

// Scratch (device globals — no runtime allocation allowed)
__device__ float g_C[BATCH * HEADS * DHEAD * DHEAD];
__device__ float g_S[BATCH * HEADS * DHEAD];
__device__ uint16_t g_Wh[384 * DIM];                        // W fp16 hi plane
__device__ uint16_t g_Wm[384 * DIM];                        // W fp16 mid plane
__device__ uint16_t g_Gh[BATCH * DIM * HID];                // G fp16
__device__ uint16_t g_qh[(size_t)BATCH * 128 * NSEQ];       // q fp16
__device__ uint16_t g_ekh[(size_t)BATCH * 128 * NSEQ];      // exp(k) fp16
__device__ uint16_t g_vh[(size_t)BATCH * 128 * NSEQ];       // v fp16

// ===================== mma.sync f16 m16n8k16 + ldmatrix + cp.async ==================
#define MMA_F16(d, a0, a1, a2, a3, b0, b1) \
    asm volatile("mma.sync.aligned.m16n8k16.row.col.f32.f16.f16.f32 " \
        "{%0,%1,%2,%3}, {%4,%5,%6,%7}, {%8,%9}, {%0,%1,%2,%3};" \
        : "+f"((d)[0]), "+f"((d)[1]), "+f"((d)[2]), "+f"((d)[3]) \
        : "r"(a0), "r"(a1), "r"(a2), "r"(a3), "r"(b0), "r"(b1))

#define LDSM_X4(r0, r1, r2, r3, addr) \
    asm volatile("ldmatrix.sync.aligned.m8n8.x4.shared.b16 {%0,%1,%2,%3}, [%4];" \
        : "=r"(r0), "=r"(r1), "=r"(r2), "=r"(r3) : "r"(addr))

#define LDSM_X4_T(r0, r1, r2, r3, addr) \
    asm volatile("ldmatrix.sync.aligned.m8n8.x4.trans.shared.b16 {%0,%1,%2,%3}, [%4];" \
        : "=r"(r0), "=r"(r1), "=r"(r2), "=r"(r3) : "r"(addr))

#define CP16(dst, src) \
    asm volatile("cp.async.cg.shared.global [%0], [%1], 16;" :: "r"(dst), "l"(src) : "memory")
#define CP_COMMIT() asm volatile("cp.async.commit_group;" ::: "memory")
#define CP_WAIT0()  asm volatile("cp.async.wait_group 0;" ::: "memory")

__device__ __forceinline__ uint32_t smem_u32(const void* p) {
    uint32_t a;
    asm("{ .reg .u64 t; cvta.to.shared.u64 t, %1; cvt.u32.u64 %0, t; }" : "=r"(a) : "l"(p));
    return a;
}
__device__ __forceinline__ uint32_t pack_f16(float lo, float hi) {
    uint32_t r;
    asm("cvt.rn.f16x2.f32 %0, %1, %2;" : "=r"(r) : "f"(hi), "f"(lo));
    return r;
}
__device__ __forceinline__ void f16_split2(float x, float y, uint32_t& hp, uint32_t& mp) {
    hp = pack_f16(x, y);
    __half2 h = *reinterpret_cast<__half2*>(&hp);
    float fx = __low2float(h);
    float fy = __high2float(h);
    mp = pack_f16(x - fx, y - fy);
}

#define AKP 40
#define BNP 136

struct PipeSmem {
    uint16_t Ah[2][128 * AKP];
    uint16_t Am[2][128 * AKP];
    uint16_t Bh[2][32 * BNP];
    uint16_t Bm[2][32 * BNP];
};
#define PIPE_SMEM ((int)sizeof(PipeSmem))

// ---------- K0: zero accumulators + split W into fp16 planes (fused) ----------
__global__ void k_init(const float* __restrict__ w) {
    int i = blockIdx.x * 256 + threadIdx.x;
    if (i < BATCH * HEADS * DHEAD * DHEAD) g_C[i] = 0.0f;
    if (i < BATCH * HEADS * DHEAD)         g_S[i] = 0.0f;
    if (i < 384 * DIM / 2) {
        float2 t = ((const float2*)w)[i];
        uint32_t h, m;
        f16_split2(t.x, t.y, h, m);
        ((uint32_t*)g_Wh)[i] = h;
        ((uint32_t*)g_Wm)[i] = m;
    }
}

// ================= mma core (128x128 tile, 8 warps 2m x 4n); MID = include cross terms ======
template <bool MID>
__device__ __forceinline__ void mma_chunk_t(uint32_t aBaseH, uint32_t aBaseM,
                                            uint32_t bBaseH, uint32_t bBaseM,
                                            float acc[4][4][4],
                                            int warp_m, int warp_n, int lane) {
    const int lr8 = lane & 15;
    const int lh  = lane >> 4;
#pragma unroll
    for (int ks = 0; ks < 2; ks++) {
        uint32_t bh[4][2], bm[4][2];
#pragma unroll
        for (int np = 0; np < 2; np++) {
            const int n0 = warp_n * 32 + np * 16;
            const uint32_t baddr = (uint32_t)((ks * 16 + lr8) * (BNP * 2) + n0 * 2 + lh * 16);
            LDSM_X4_T(bh[np * 2][0], bh[np * 2][1], bh[np * 2 + 1][0], bh[np * 2 + 1][1],
                      bBaseH + baddr);
            if (MID)
                LDSM_X4_T(bm[np * 2][0], bm[np * 2][1], bm[np * 2 + 1][0], bm[np * 2 + 1][1],
                          bBaseM + baddr);
        }
#pragma unroll
        for (int mt = 0; mt < 4; mt++) {
            const int m0 = warp_m * 64 + mt * 16;
            const uint32_t aaddr = (uint32_t)((m0 + lr8) * (AKP * 2) + ks * 32 + lh * 16);
            uint32_t ah0, ah1, ah2, ah3;
            LDSM_X4(ah0, ah1, ah2, ah3, aBaseH + aaddr);
            uint32_t am0, am1, am2, am3;
            if (MID) LDSM_X4(am0, am1, am2, am3, aBaseM + aaddr);
#pragma unroll
            for (int nt = 0; nt < 4; nt++) {
                MMA_F16(acc[mt][nt], ah0, ah1, ah2, ah3, bh[nt][0], bh[nt][1]);
                if (MID) {
                    MMA_F16(acc[mt][nt], ah0, ah1, ah2, ah3, bm[nt][0], bm[nt][1]);
                    MMA_F16(acc[mt][nt], am0, am1, am2, am3, bh[nt][0], bh[nt][1]);
                }
            }
        }
    }
}

// ---------- K1: qkv = w_qkv @ x  (q/v: 1-pass fp16, k: 3-pass fp16); hi-only outputs ----------
__global__ __launch_bounds__(256, 2) void k_qkv_mma(const float* __restrict__ x) {
    extern __shared__ char dsm[];
    PipeSmem* s = (PipeSmem*)dsm;
    const int b       = blockIdx.z;
    const int grp     = blockIdx.y;            // 0=q, 1=k, 2=v
    const int nBase   = blockIdx.x * 128;
    const int tid     = threadIdx.x;
    const int lane    = tid & 31;
    const int wid     = tid >> 5;
    const int warp_m  = wid & 1;
    const int warp_n  = wid >> 1;

    const float* xb = x + (size_t)b * DIM * NSEQ + nBase;
    const uint16_t* WhA = g_Wh + (size_t)(grp * 128) * DIM;
    const uint16_t* WmA = g_Wm + (size_t)(grp * 128) * DIM;

    float acc[4][4][4];
#pragma unroll
    for (int i = 0; i < 4; i++)
#pragma unroll
        for (int j = 0; j < 4; j++)
#pragma unroll
            for (int c = 0; c < 4; c++) acc[i][j][c] = 0.0f;

    const int kb = tid >> 5;
    const int n4 = (tid & 31) << 2;
    const int ar = tid >> 2, asg = tid & 3;

    auto issueA = [&](int st, int k0) {
#pragma unroll
        for (int half = 0; half < 2; half++) {
            const int r = ar + half * 64;
            CP16(smem_u32(&s->Ah[st][r * AKP + asg * 8]), WhA + (size_t)r * DIM + k0 + asg * 8);
            if (grp == 1)
                CP16(smem_u32(&s->Am[st][r * AKP + asg * 8]), WmA + (size_t)r * DIM + k0 + asg * 8);
        }
        CP_COMMIT();
    };
    auto ldgB = [&](float4 pb[4], int k0) {
#pragma unroll
        for (int it = 0; it < 4; it++)
            pb[it] = *(const float4*)(xb + (size_t)(k0 + kb + it * 8) * NSEQ + n4);
    };
    auto cvtB = [&](int st, const float4 pb[4]) {
#pragma unroll
        for (int it = 0; it < 4; it++) {
            const int k = kb + it * 8;
            if (grp == 1) {
                uint32_t h01, m01, h23, m23;
                f16_split2(pb[it].x, pb[it].y, h01, m01);
                f16_split2(pb[it].z, pb[it].w, h23, m23);
                *(uint2*)&s->Bh[st][k * BNP + n4] = make_uint2(h01, h23);
                *(uint2*)&s->Bm[st][k * BNP + n4] = make_uint2(m01, m23);
            } else {
                *(uint2*)&s->Bh[st][k * BNP + n4] =
                    make_uint2(pack_f16(pb[it].x, pb[it].y), pack_f16(pb[it].z, pb[it].w));
            }
        }
    };

    float4 pb[4];
    ldgB(pb, 0);
    issueA(0, 0);

    for (int chunk = 0; chunk < 8; chunk++) {
        const int cur = chunk & 1;
        CP_WAIT0();
        cvtB(cur, pb);
        __syncthreads();
        if (chunk < 7) {
            ldgB(pb, (chunk + 1) * 32);
            issueA(cur ^ 1, (chunk + 1) * 32);
        }
        if (grp == 1)
            mma_chunk_t<true>(smem_u32(s->Ah[cur]), smem_u32(s->Am[cur]),
                              smem_u32(s->Bh[cur]), smem_u32(s->Bm[cur]),
                              acc, warp_m, warp_n, lane);
        else
            mma_chunk_t<false>(smem_u32(s->Ah[cur]), smem_u32(s->Am[cur]),
                               smem_u32(s->Bh[cur]), smem_u32(s->Bm[cur]),
                               acc, warp_m, warp_n, lane);
    }

    const int lg = lane >> 2, lc = lane & 3;
    uint16_t* dstH = (grp == 0) ? g_qh : (grp == 1) ? g_ekh : g_vh;

    float sr0[4] = {0.f, 0.f, 0.f, 0.f};
    float sr8[4] = {0.f, 0.f, 0.f, 0.f};
#pragma unroll
    for (int mt = 0; mt < 4; mt++) {
        const int row0 = warp_m * 64 + mt * 16 + lg;
#pragma unroll
        for (int nt = 0; nt < 4; nt++) {
            const int cn = nBase + warp_n * 32 + nt * 8 + (lc << 1);
            float v0 = acc[mt][nt][0], v1 = acc[mt][nt][1];
            float v2 = acc[mt][nt][2], v3 = acc[mt][nt][3];
            if (grp == 1) {
                v0 = __expf(v0); v1 = __expf(v1); v2 = __expf(v2); v3 = __expf(v3);
                sr0[mt] += v0 + v1;
                sr8[mt] += v2 + v3;
            }
            const size_t wi0 = (((size_t)b * 128 + row0) * NSEQ + cn) >> 1;
            const size_t wi1 = (((size_t)b * 128 + row0 + 8) * NSEQ + cn) >> 1;
            ((uint32_t*)dstH)[wi0] = pack_f16(v0, v1);
            ((uint32_t*)dstH)[wi1] = pack_f16(v2, v3);
        }
    }
    if (grp == 1) {
#pragma unroll
        for (int mt = 0; mt < 4; mt++) {
            float s0 = sr0[mt], s8 = sr8[mt];
            s0 += __shfl_xor_sync(0xFFFFFFFFu, s0, 1);
            s0 += __shfl_xor_sync(0xFFFFFFFFu, s0, 2);
            s8 += __shfl_xor_sync(0xFFFFFFFFu, s8, 1);
            s8 += __shfl_xor_sync(0xFFFFFFFFu, s8, 2);
            if (lc == 0) {
                const int row0 = warp_m * 64 + mt * 16 + lg;
                atomicAdd(&g_S[b * 128 + row0], s0);
                atomicAdd(&g_S[b * 128 + row0 + 8], s8);
            }
        }
    }
}

// ---------- K2: C[b,h] += ek-slab @ v-slab^T (1-pass fp16, cp.async pipelined) ----------
struct CtxSmem {
    uint16_t Ekh[2][32 * BNP];
    uint16_t Vh[2][32 * BNP];
};
#define CTX_SMEM ((int)sizeof(CtxSmem))

__global__ __launch_bounds__(256, 3) void k_ctx_mma() {
    extern __shared__ char dsm[];
    CtxSmem* s = (CtxSmem*)dsm;
    __shared__ float Cred[32 * 32];

    const int slab = blockIdx.x, h = blockIdx.y, b = blockIdx.z;
    const int tid  = threadIdx.x;
    const int lane = tid & 31;
    const int wid  = tid >> 5;
    const int lg = lane >> 2, lc = lane & 3;
    const int lr8 = lane & 15, lh = lane >> 4;

    for (int i = tid; i < 1024; i += 256) Cred[i] = 0.0f;

    const size_t rowb = (size_t)b * 128 + h * 32;
    const size_t noff = (size_t)slab * 512;
    const uint16_t* ekh = g_ekh + rowb * NSEQ + noff;
    const uint16_t* vh  = g_vh  + rowb * NSEQ + noff;

    float acc[2][4][4];
#pragma unroll
    for (int i = 0; i < 2; i++)
#pragma unroll
        for (int j = 0; j < 4; j++)
#pragma unroll
            for (int c = 0; c < 4; c++) acc[i][j][c] = 0.0f;

    const int cr = tid >> 4, csg = tid & 15;

    auto issue = [&](int st, int chunk) {
        const int cn = chunk * 128;
#pragma unroll
        for (int it = 0; it < 2; it++) {
            const int r = cr + it * 16;
            const size_t so = (size_t)r * NSEQ + cn + csg * 8;
            const uint32_t doff = (uint32_t)(r * BNP + csg * 8) * 2;
            CP16(smem_u32(s->Ekh[st]) + doff, ekh + so);
            CP16(smem_u32(s->Vh[st]) + doff,  vh + so);
        }
        CP_COMMIT();
    };

    issue(0, 0);

    for (int chunk = 0; chunk < 4; chunk++) {
        const int cur = chunk & 1;
        CP_WAIT0();
        __syncthreads();
        if (chunk < 3) issue(cur ^ 1, chunk + 1);

        uint32_t bh[4][2];
        {
            const int e    = (lane & 7) + ((lane >> 4) << 3);
            const int koff = ((lane >> 3) & 1) << 3;
#pragma unroll
            for (int np = 0; np < 2; np++) {
                const uint32_t baddr =
                    (uint32_t)((np * 16 + e) * (BNP * 2) + (wid * 16 + koff) * 2);
                LDSM_X4(bh[np * 2][0], bh[np * 2][1], bh[np * 2 + 1][0], bh[np * 2 + 1][1],
                        smem_u32(s->Vh[cur]) + baddr);
            }
        }
#pragma unroll
        for (int mt = 0; mt < 2; mt++) {
            const uint32_t aaddr = (uint32_t)((mt * 16 + lr8) * (BNP * 2) + wid * 32 + lh * 16);
            uint32_t ah0, ah1, ah2, ah3;
            LDSM_X4(ah0, ah1, ah2, ah3, smem_u32(s->Ekh[cur]) + aaddr);
#pragma unroll
            for (int nt = 0; nt < 4; nt++)
                MMA_F16(acc[mt][nt], ah0, ah1, ah2, ah3, bh[nt][0], bh[nt][1]);
        }
    }

    __syncthreads();
#pragma unroll
    for (int mt = 0; mt < 2; mt++) {
        const int d = mt * 16 + lg;
#pragma unroll
        for (int nt = 0; nt < 4; nt++) {
            const int e = nt * 8 + (lc << 1);
            atomicAdd(&Cred[d * 32 + e],           acc[mt][nt][0]);
            atomicAdd(&Cred[d * 32 + e + 1],       acc[mt][nt][1]);
            atomicAdd(&Cred[(d + 8) * 32 + e],     acc[mt][nt][2]);
            atomicAdd(&Cred[(d + 8) * 32 + e + 1], acc[mt][nt][3]);
        }
    }
    __syncthreads();
    float* Cg = g_C + (size_t)(b * HEADS + h) * 1024;
    for (int i = tid; i < 1024; i += 256) atomicAdd(&Cg[i], Cred[i]);
}

// ---------- K3: G = (w_out-slice @ C)/S -> fp16 (R14 layout: 128 thr, 2 o-halves) ----------
__global__ __launch_bounds__(128) void k_G(const float* __restrict__ w_out) {
    const int h = blockIdx.x, b = blockIdx.y;
    const int o = blockIdx.z * 128 + threadIdx.x;

    __shared__ float Cs[DHEAD * DHEAD];
    __shared__ float Si[DHEAD];

    for (int i = threadIdx.x; i < DHEAD * DHEAD; i += 128)
        Cs[i] = g_C[(size_t)(b * HEADS + h) * DHEAD * DHEAD + i];
    if (threadIdx.x < DHEAD)
        Si[threadIdx.x] = __frcp_rn(g_S[b * 128 + h * DHEAD + threadIdx.x]);
    __syncthreads();

    float wr[DHEAD];
#pragma unroll
    for (int e4 = 0; e4 < DHEAD; e4 += 4) {
        float4 t = *(const float4*)(w_out + (size_t)o * HID + h * DHEAD + e4);
        wr[e4] = t.x; wr[e4 + 1] = t.y; wr[e4 + 2] = t.z; wr[e4 + 3] = t.w;
    }
    const size_t gbase = (size_t)(b * DIM + o) * HID + h * DHEAD;
#pragma unroll 2
    for (int d = 0; d < DHEAD; d += 2) {
        float a0 = 0.f, a1 = 0.f;
#pragma unroll
        for (int e = 0; e < DHEAD; e++) {
            a0 += wr[e] * Cs[d * DHEAD + e];
            a1 += wr[e] * Cs[(d + 1) * DHEAD + e];
        }
        a0 *= Si[d]; a1 *= Si[d + 1];
        ((uint32_t*)g_Gh)[(gbase + d) >> 1] = pack_f16(a0, a1);
    }
}

// ---------- K4: out = G_b @ q_b + b_out (1-pass fp16) ----------
struct K4Smem {
    uint16_t Ah[2][128 * AKP];
    uint16_t Bh[2][32 * BNP];
};
#define K4_SMEM ((int)sizeof(K4Smem))

__global__ __launch_bounds__(256, 2) void k_out_mma(const float* __restrict__ bias,
                                                    float* __restrict__ out) {
    extern __shared__ char dsm[];
    K4Smem* s = (K4Smem*)dsm;
    const int b       = blockIdx.z;
    const int rowBase = blockIdx.y * 128;
    const int nBase   = blockIdx.x * 128;
    const int tid     = threadIdx.x;
    const int lane    = tid & 31;
    const int wid     = tid >> 5;
    const int warp_m  = wid & 1;
    const int warp_n  = wid >> 1;

    const uint16_t* GhA = g_Gh + (size_t)(b * DIM + rowBase) * HID;
    const uint16_t* qhB = g_qh + (size_t)b * 128 * NSEQ + nBase;

    float acc[4][4][4];
#pragma unroll
    for (int i = 0; i < 4; i++)
#pragma unroll
        for (int j = 0; j < 4; j++)
#pragma unroll
            for (int c = 0; c < 4; c++) acc[i][j][c] = 0.0f;

    const int ar = tid >> 2, asg = tid & 3;
    const int bk = tid >> 4, bsg = tid & 15;

    auto issue = [&](int st, int k0) {
#pragma unroll
        for (int half = 0; half < 2; half++) {
            const int r = ar + half * 64;
            CP16(smem_u32(&s->Ah[st][r * AKP + asg * 8]), GhA + (size_t)r * HID + k0 + asg * 8);
        }
#pragma unroll
        for (int half = 0; half < 2; half++) {
            const int k = bk + half * 16;
            CP16(smem_u32(&s->Bh[st][k * BNP + bsg * 8]), qhB + (size_t)(k0 + k) * NSEQ + bsg * 8);
        }
        CP_COMMIT();
    };

    issue(0, 0);

    for (int chunk = 0; chunk < 4; chunk++) {
        const int cur = chunk & 1;
        CP_WAIT0();
        __syncthreads();
        if (chunk < 3) issue(cur ^ 1, (chunk + 1) * 32);
        mma_chunk_t<false>(smem_u32(s->Ah[cur]), 0u,
                           smem_u32(s->Bh[cur]), 0u,
                           acc, warp_m, warp_n, lane);
    }

    const int lg = lane >> 2, lc = lane & 3;
    float* outb = out + (size_t)b * DIM * NSEQ;
#pragma unroll
    for (int mt = 0; mt < 4; mt++) {
        const int row0 = rowBase + warp_m * 64 + mt * 16 + lg;
        const float bi0 = bias[row0], bi1 = bias[row0 + 8];
#pragma unroll
        for (int nt = 0; nt < 4; nt++) {
            const int cn = nBase + warp_n * 32 + nt * 8 + (lc << 1);
            *(float2*)(outb + (size_t)row0 * NSEQ + cn) =
                make_float2(acc[mt][nt][0] + bi0, acc[mt][nt][1] + bi0);
            *(float2*)(outb + (size_t)(row0 + 8) * NSEQ + cn) =
                make_float2(acc[mt][nt][2] + bi1, acc[mt][nt][3] + bi1);
        }
    }
}

extern "C" void kernel_launch(void* const* d_in, const int* in_sizes, int n_in,
                              void* d_out, int out_size) {
    const float* x     = (const float*)d_in[0];
    const float* w_qkv = (const float*)d_in[1];
    const float* w_out = (const float*)d_in[2];
    const float* b_out = (const float*)d_in[3];
    float* out = (float*)d_out;

    cudaFuncSetAttribute(k_qkv_mma, cudaFuncAttributeMaxDynamicSharedMemorySize, PIPE_SMEM);
    cudaFuncSetAttribute(k_ctx_mma, cudaFuncAttributeMaxDynamicSharedMemorySize, CTX_SMEM);
    cudaFuncSetAttribute(k_out_mma, cudaFuncAttributeMaxDynamicSharedMemorySize, K4_SMEM);

    k_init<<<257, 256>>>(w_qkv);                 // zeros all g_C/g_S + W planes, every replay
    k_qkv_mma<<<dim3(NSEQ / 128, 3, BATCH), 256, PIPE_SMEM>>>(x);
    k_ctx_mma<<<dim3(16, HEADS, BATCH), 256, CTX_SMEM>>>();
    k_G<<<dim3(HEADS, BATCH, 2), 128>>>(w_out);
    k_out_mma<<<dim3(NSEQ / 128, 2, BATCH), 256, K4_SMEM>>>(b_out, out);
}

// round 17
// speedup vs baseline: 1.3573x; 1.2181x over previous
#include <cuda_runtime.h>
#include <cuda_fp16.h>
#include <cstdint>

#define BATCH 16
#define DIM   256
#define NSEQ  8192
#define HEADS 4
#define DHEAD 32
#define HID   128

// Scratch (device globals — no runtime allocation allowed)
__device__ float g_C[BATCH * HEADS * DHEAD * DHEAD];
__device__ float g_S[BATCH * HEADS * DHEAD];
__device__ uint16_t g_Wh[384 * DIM];                        // W fp16
__device__ uint16_t g_Gh[BATCH * DIM * HID];                // G fp16
__device__ uint16_t g_qh[(size_t)BATCH * 128 * NSEQ];       // q fp16
__device__ uint16_t g_ekh[(size_t)BATCH * 128 * NSEQ];      // exp(k) fp16
__device__ uint16_t g_vh[(size_t)BATCH * 128 * NSEQ];       // v fp16

// ===================== mma.sync f16 m16n8k16 + ldmatrix + cp.async ==================
#define MMA_F16(d, a0, a1, a2, a3, b0, b1) \
    asm volatile("mma.sync.aligned.m16n8k16.row.col.f32.f16.f16.f32 " \
        "{%0,%1,%2,%3}, {%4,%5,%6,%7}, {%8,%9}, {%0,%1,%2,%3};" \
        : "+f"((d)[0]), "+f"((d)[1]), "+f"((d)[2]), "+f"((d)[3]) \
        : "r"(a0), "r"(a1), "r"(a2), "r"(a3), "r"(b0), "r"(b1))

#define LDSM_X4(r0, r1, r2, r3, addr) \
    asm volatile("ldmatrix.sync.aligned.m8n8.x4.shared.b16 {%0,%1,%2,%3}, [%4];" \
        : "=r"(r0), "=r"(r1), "=r"(r2), "=r"(r3) : "r"(addr))

#define LDSM_X4_T(r0, r1, r2, r3, addr) \
    asm volatile("ldmatrix.sync.aligned.m8n8.x4.trans.shared.b16 {%0,%1,%2,%3}, [%4];" \
        : "=r"(r0), "=r"(r1), "=r"(r2), "=r"(r3) : "r"(addr))

#define CP16(dst, src) \
    asm volatile("cp.async.cg.shared.global [%0], [%1], 16;" :: "r"(dst), "l"(src) : "memory")
#define CP_COMMIT() asm volatile("cp.async.commit_group;" ::: "memory")
#define CP_WAIT0()  asm volatile("cp.async.wait_group 0;" ::: "memory")

__device__ __forceinline__ uint32_t smem_u32(const void* p) {
    uint32_t a;
    asm("{ .reg .u64 t; cvta.to.shared.u64 t, %1; cvt.u32.u64 %0, t; }" : "=r"(a) : "l"(p));
    return a;
}
__device__ __forceinline__ uint32_t pack_f16(float lo, float hi) {
    uint32_t r;
    asm("cvt.rn.f16x2.f32 %0, %1, %2;" : "=r"(r) : "f"(hi), "f"(lo));
    return r;
}

#define AKP 40
#define BNP 136

struct PipeSmem {
    uint16_t Ah[2][128 * AKP];
    uint16_t Bh[2][32 * BNP];
};
#define PIPE_SMEM ((int)sizeof(PipeSmem))   // 37888

// ---------- K0: zero accumulators + W -> fp16 (fused) ----------
__global__ void k_init(const float* __restrict__ w) {
    int i = blockIdx.x * 256 + threadIdx.x;
    if (i < BATCH * HEADS * DHEAD * DHEAD) g_C[i] = 0.0f;
    if (i < BATCH * HEADS * DHEAD)         g_S[i] = 0.0f;
    if (i < 384 * DIM / 2) {
        float2 t = ((const float2*)w)[i];
        ((uint32_t*)g_Wh)[i] = pack_f16(t.x, t.y);
    }
}

// ================= mma core (128x128 tile, 8 warps 2m x 4n), 1-pass ======
__device__ __forceinline__ void mma_chunk(uint32_t aBase, uint32_t bBase,
                                          float acc[4][4][4],
                                          int warp_m, int warp_n, int lane) {
    const int lr8 = lane & 15;
    const int lh  = lane >> 4;
#pragma unroll
    for (int ks = 0; ks < 2; ks++) {
        uint32_t bh[4][2];
#pragma unroll
        for (int np = 0; np < 2; np++) {
            const int n0 = warp_n * 32 + np * 16;
            const uint32_t baddr = (uint32_t)((ks * 16 + lr8) * (BNP * 2) + n0 * 2 + lh * 16);
            LDSM_X4_T(bh[np * 2][0], bh[np * 2][1], bh[np * 2 + 1][0], bh[np * 2 + 1][1],
                      bBase + baddr);
        }
#pragma unroll
        for (int mt = 0; mt < 4; mt++) {
            const int m0 = warp_m * 64 + mt * 16;
            const uint32_t aaddr = (uint32_t)((m0 + lr8) * (AKP * 2) + ks * 32 + lh * 16);
            uint32_t ah0, ah1, ah2, ah3;
            LDSM_X4(ah0, ah1, ah2, ah3, aBase + aaddr);
#pragma unroll
            for (int nt = 0; nt < 4; nt++)
                MMA_F16(acc[mt][nt], ah0, ah1, ah2, ah3, bh[nt][0], bh[nt][1]);
        }
    }
}

// ---------- K1: qkv = w_qkv @ x  (all groups 1-pass fp16) ----------
__global__ __launch_bounds__(256, 2) void k_qkv_mma(const float* __restrict__ x) {
    extern __shared__ char dsm[];
    PipeSmem* s = (PipeSmem*)dsm;
    const int b       = blockIdx.z;
    const int grp     = blockIdx.y;            // 0=q, 1=k, 2=v
    const int nBase   = blockIdx.x * 128;
    const int tid     = threadIdx.x;
    const int lane    = tid & 31;
    const int wid     = tid >> 5;
    const int warp_m  = wid & 1;
    const int warp_n  = wid >> 1;

    const float* xb = x + (size_t)b * DIM * NSEQ + nBase;
    const uint16_t* WhA = g_Wh + (size_t)(grp * 128) * DIM;

    float acc[4][4][4];
#pragma unroll
    for (int i = 0; i < 4; i++)
#pragma unroll
        for (int j = 0; j < 4; j++)
#pragma unroll
            for (int c = 0; c < 4; c++) acc[i][j][c] = 0.0f;

    const int kb = tid >> 5;
    const int n4 = (tid & 31) << 2;
    const int ar = tid >> 2, asg = tid & 3;

    auto issueA = [&](int st, int k0) {
#pragma unroll
        for (int half = 0; half < 2; half++) {
            const int r = ar + half * 64;
            CP16(smem_u32(&s->Ah[st][r * AKP + asg * 8]), WhA + (size_t)r * DIM + k0 + asg * 8);
        }
        CP_COMMIT();
    };
    auto ldgB = [&](float4 pb[4], int k0) {
#pragma unroll
        for (int it = 0; it < 4; it++)
            pb[it] = *(const float4*)(xb + (size_t)(k0 + kb + it * 8) * NSEQ + n4);
    };
    auto cvtB = [&](int st, const float4 pb[4]) {
#pragma unroll
        for (int it = 0; it < 4; it++) {
            const int k = kb + it * 8;
            *(uint2*)&s->Bh[st][k * BNP + n4] =
                make_uint2(pack_f16(pb[it].x, pb[it].y), pack_f16(pb[it].z, pb[it].w));
        }
    };

    float4 pb[4];
    ldgB(pb, 0);
    issueA(0, 0);

    for (int chunk = 0; chunk < 8; chunk++) {
        const int cur = chunk & 1;
        CP_WAIT0();
        cvtB(cur, pb);
        __syncthreads();
        if (chunk < 7) {
            ldgB(pb, (chunk + 1) * 32);
            issueA(cur ^ 1, (chunk + 1) * 32);
        }
        mma_chunk(smem_u32(s->Ah[cur]), smem_u32(s->Bh[cur]),
                  acc, warp_m, warp_n, lane);
    }

    const int lg = lane >> 2, lc = lane & 3;
    uint16_t* dstH = (grp == 0) ? g_qh : (grp == 1) ? g_ekh : g_vh;

    float sr0[4] = {0.f, 0.f, 0.f, 0.f};
    float sr8[4] = {0.f, 0.f, 0.f, 0.f};
#pragma unroll
    for (int mt = 0; mt < 4; mt++) {
        const int row0 = warp_m * 64 + mt * 16 + lg;
#pragma unroll
        for (int nt = 0; nt < 4; nt++) {
            const int cn = nBase + warp_n * 32 + nt * 8 + (lc << 1);
            float v0 = acc[mt][nt][0], v1 = acc[mt][nt][1];
            float v2 = acc[mt][nt][2], v3 = acc[mt][nt][3];
            if (grp == 1) {
                v0 = __expf(v0); v1 = __expf(v1); v2 = __expf(v2); v3 = __expf(v3);
                sr0[mt] += v0 + v1;
                sr8[mt] += v2 + v3;
            }
            const size_t wi0 = (((size_t)b * 128 + row0) * NSEQ + cn) >> 1;
            const size_t wi1 = (((size_t)b * 128 + row0 + 8) * NSEQ + cn) >> 1;
            ((uint32_t*)dstH)[wi0] = pack_f16(v0, v1);
            ((uint32_t*)dstH)[wi1] = pack_f16(v2, v3);
        }
    }
    if (grp == 1) {
#pragma unroll
        for (int mt = 0; mt < 4; mt++) {
            float s0 = sr0[mt], s8 = sr8[mt];
            s0 += __shfl_xor_sync(0xFFFFFFFFu, s0, 1);
            s0 += __shfl_xor_sync(0xFFFFFFFFu, s0, 2);
            s8 += __shfl_xor_sync(0xFFFFFFFFu, s8, 1);
            s8 += __shfl_xor_sync(0xFFFFFFFFu, s8, 2);
            if (lc == 0) {
                const int row0 = warp_m * 64 + mt * 16 + lg;
                atomicAdd(&g_S[b * 128 + row0], s0);
                atomicAdd(&g_S[b * 128 + row0 + 8], s8);
            }
        }
    }
}

// ---------- K2: C[b,h] += ek-slab @ v-slab^T (1-pass fp16, cp.async pipelined) ----------
struct CtxSmem {
    uint16_t Ekh[2][32 * BNP];
    uint16_t Vh[2][32 * BNP];
};
#define CTX_SMEM ((int)sizeof(CtxSmem))

__global__ __launch_bounds__(256, 3) void k_ctx_mma() {
    extern __shared__ char dsm[];
    CtxSmem* s = (CtxSmem*)dsm;
    __shared__ float Cred[32 * 32];

    const int slab = blockIdx.x, h = blockIdx.y, b = blockIdx.z;
    const int tid  = threadIdx.x;
    const int lane = tid & 31;
    const int wid  = tid >> 5;
    const int lg = lane >> 2, lc = lane & 3;
    const int lr8 = lane & 15, lh = lane >> 4;

    for (int i = tid; i < 1024; i += 256) Cred[i] = 0.0f;

    const size_t rowb = (size_t)b * 128 + h * 32;
    const size_t noff = (size_t)slab * 512;
    const uint16_t* ekh = g_ekh + rowb * NSEQ + noff;
    const uint16_t* vh  = g_vh  + rowb * NSEQ + noff;

    float acc[2][4][4];
#pragma unroll
    for (int i = 0; i < 2; i++)
#pragma unroll
        for (int j = 0; j < 4; j++)
#pragma unroll
            for (int c = 0; c < 4; c++) acc[i][j][c] = 0.0f;

    const int cr = tid >> 4, csg = tid & 15;

    auto issue = [&](int st, int chunk) {
        const int cn = chunk * 128;
#pragma unroll
        for (int it = 0; it < 2; it++) {
            const int r = cr + it * 16;
            const size_t so = (size_t)r * NSEQ + cn + csg * 8;
            const uint32_t doff = (uint32_t)(r * BNP + csg * 8) * 2;
            CP16(smem_u32(s->Ekh[st]) + doff, ekh + so);
            CP16(smem_u32(s->Vh[st]) + doff,  vh + so);
        }
        CP_COMMIT();
    };

    issue(0, 0);

    for (int chunk = 0; chunk < 4; chunk++) {
        const int cur = chunk & 1;
        CP_WAIT0();
        __syncthreads();
        if (chunk < 3) issue(cur ^ 1, chunk + 1);

        uint32_t bh[4][2];
        {
            const int e    = (lane & 7) + ((lane >> 4) << 3);
            const int koff = ((lane >> 3) & 1) << 3;
#pragma unroll
            for (int np = 0; np < 2; np++) {
                const uint32_t baddr =
                    (uint32_t)((np * 16 + e) * (BNP * 2) + (wid * 16 + koff) * 2);
                LDSM_X4(bh[np * 2][0], bh[np * 2][1], bh[np * 2 + 1][0], bh[np * 2 + 1][1],
                        smem_u32(s->Vh[cur]) + baddr);
            }
        }
#pragma unroll
        for (int mt = 0; mt < 2; mt++) {
            const uint32_t aaddr = (uint32_t)((mt * 16 + lr8) * (BNP * 2) + wid * 32 + lh * 16);
            uint32_t ah0, ah1, ah2, ah3;
            LDSM_X4(ah0, ah1, ah2, ah3, smem_u32(s->Ekh[cur]) + aaddr);
#pragma unroll
            for (int nt = 0; nt < 4; nt++)
                MMA_F16(acc[mt][nt], ah0, ah1, ah2, ah3, bh[nt][0], bh[nt][1]);
        }
    }

    __syncthreads();
#pragma unroll
    for (int mt = 0; mt < 2; mt++) {
        const int d = mt * 16 + lg;
#pragma unroll
        for (int nt = 0; nt < 4; nt++) {
            const int e = nt * 8 + (lc << 1);
            atomicAdd(&Cred[d * 32 + e],           acc[mt][nt][0]);
            atomicAdd(&Cred[d * 32 + e + 1],       acc[mt][nt][1]);
            atomicAdd(&Cred[(d + 8) * 32 + e],     acc[mt][nt][2]);
            atomicAdd(&Cred[(d + 8) * 32 + e + 1], acc[mt][nt][3]);
        }
    }
    __syncthreads();
    float* Cg = g_C + (size_t)(b * HEADS + h) * 1024;
    for (int i = tid; i < 1024; i += 256) atomicAdd(&Cg[i], Cred[i]);
}

// ---------- K3: G = (w_out-slice @ C)/S -> fp16 (128 thr, 2 o-halves) ----------
__global__ __launch_bounds__(128) void k_G(const float* __restrict__ w_out) {
    const int h = blockIdx.x, b = blockIdx.y;
    const int o = blockIdx.z * 128 + threadIdx.x;

    __shared__ float Cs[DHEAD * DHEAD];
    __shared__ float Si[DHEAD];

    for (int i = threadIdx.x; i < DHEAD * DHEAD; i += 128)
        Cs[i] = g_C[(size_t)(b * HEADS + h) * DHEAD * DHEAD + i];
    if (threadIdx.x < DHEAD)
        Si[threadIdx.x] = __frcp_rn(g_S[b * 128 + h * DHEAD + threadIdx.x]);
    __syncthreads();

    float wr[DHEAD];
#pragma unroll
    for (int e4 = 0; e4 < DHEAD; e4 += 4) {
        float4 t = *(const float4*)(w_out + (size_t)o * HID + h * DHEAD + e4);
        wr[e4] = t.x; wr[e4 + 1] = t.y; wr[e4 + 2] = t.z; wr[e4 + 3] = t.w;
    }
    const size_t gbase = (size_t)(b * DIM + o) * HID + h * DHEAD;
#pragma unroll 2
    for (int d = 0; d < DHEAD; d += 2) {
        float a0 = 0.f, a1 = 0.f;
#pragma unroll
        for (int e = 0; e < DHEAD; e++) {
            a0 += wr[e] * Cs[d * DHEAD + e];
            a1 += wr[e] * Cs[(d + 1) * DHEAD + e];
        }
        a0 *= Si[d]; a1 *= Si[d + 1];
        ((uint32_t*)g_Gh)[(gbase + d) >> 1] = pack_f16(a0, a1);
    }
}

// ---------- K4: out = G_b @ q_b + b_out (1-pass fp16) ----------
__global__ __launch_bounds__(256, 2) void k_out_mma(const float* __restrict__ bias,
                                                    float* __restrict__ out) {
    extern __shared__ char dsm[];
    PipeSmem* s = (PipeSmem*)dsm;
    const int b       = blockIdx.z;
    const int rowBase = blockIdx.y * 128;
    const int nBase   = blockIdx.x * 128;
    const int tid     = threadIdx.x;
    const int lane    = tid & 31;
    const int wid     = tid >> 5;
    const int warp_m  = wid & 1;
    const int warp_n  = wid >> 1;

    const uint16_t* GhA = g_Gh + (size_t)(b * DIM + rowBase) * HID;
    const uint16_t* qhB = g_qh + (size_t)b * 128 * NSEQ + nBase;

    float acc[4][4][4];
#pragma unroll
    for (int i = 0; i < 4; i++)
#pragma unroll
        for (int j = 0; j < 4; j++)
#pragma unroll
            for (int c = 0; c < 4; c++) acc[i][j][c] = 0.0f;

    const int ar = tid >> 2, asg = tid & 3;
    const int bk = tid >> 4, bsg = tid & 15;

    auto issue = [&](int st, int k0) {
#pragma unroll
        for (int half = 0; half < 2; half++) {
            const int r = ar + half * 64;
            CP16(smem_u32(&s->Ah[st][r * AKP + asg * 8]), GhA + (size_t)r * HID + k0 + asg * 8);
        }
#pragma unroll
        for (int half = 0; half < 2; half++) {
            const int k = bk + half * 16;
            CP16(smem_u32(&s->Bh[st][k * BNP + bsg * 8]), qhB + (size_t)(k0 + k) * NSEQ + bsg * 8);
        }
        CP_COMMIT();
    };

    issue(0, 0);

    for (int chunk = 0; chunk < 4; chunk++) {
        const int cur = chunk & 1;
        CP_WAIT0();
        __syncthreads();
        if (chunk < 3) issue(cur ^ 1, (chunk + 1) * 32);
        mma_chunk(smem_u32(s->Ah[cur]), smem_u32(s->Bh[cur]),
                  acc, warp_m, warp_n, lane);
    }

    const int lg = lane >> 2, lc = lane & 3;
    float* outb = out + (size_t)b * DIM * NSEQ;
#pragma unroll
    for (int mt = 0; mt < 4; mt++) {
        const int row0 = rowBase + warp_m * 64 + mt * 16 + lg;
        const float bi0 = bias[row0], bi1 = bias[row0 + 8];
#pragma unroll
        for (int nt = 0; nt < 4; nt++) {
            const int cn = nBase + warp_n * 32 + nt * 8 + (lc << 1);
            *(float2*)(outb + (size_t)row0 * NSEQ + cn) =
                make_float2(acc[mt][nt][0] + bi0, acc[mt][nt][1] + bi0);
            *(float2*)(outb + (size_t)(row0 + 8) * NSEQ + cn) =
                make_float2(acc[mt][nt][2] + bi1, acc[mt][nt][3] + bi1);
        }
    }
}

extern "C" void kernel_launch(void* const* d_in, const int* in_sizes, int n_in,
                              void* d_out, int out_size) {
    const float* x     = (const float*)d_in[0];
    const float* w_qkv = (const float*)d_in[1];
    const float* w_out = (const float*)d_in[2];
    const float* b_out = (const float*)d_in[3];
    float* out = (float*)d_out;

    cudaFuncSetAttribute(k_qkv_mma, cudaFuncAttributeMaxDynamicSharedMemorySize, PIPE_SMEM);
    cudaFuncSetAttribute(k_ctx_mma, cudaFuncAttributeMaxDynamicSharedMemorySize, CTX_SMEM);
    cudaFuncSetAttribute(k_out_mma, cudaFuncAttributeMaxDynamicSharedMemorySize, PIPE_SMEM);

    k_init<<<257, 256>>>(w_qkv);                 // zeros all g_C/g_S + W fp16, every replay
    k_qkv_mma<<<dim3(NSEQ / 128, 3, BATCH), 256, PIPE_SMEM>>>(x);
    k_ctx_mma<<<dim3(16, HEADS, BATCH), 256, CTX_SMEM>>>();
    k_G<<<dim3(HEADS, BATCH, 2), 128>>>(w_out);
    k_out_mma<<<dim3(NSEQ / 128, 2, BATCH), 256, PIPE_SMEM>>>(b_out, out);
}